// round 15
// baseline (speedup 1.0000x reference)
#include <cuda_runtime.h>

#define NB    256
#define NS    64
#define KACT  8
#define INF_  1024
#define OUTF  1024
#define SUBF  128
#define QF    1024
#define NASG  (NB * KACT)
#define KQ    8                // k-split of T (128 i per task)
#define RPI   32               // rows per work item
#define MAXITEMS 128
#define VSTR  36               // smem row pitch (floats)
#define GRIDN 296              // 2 CTAs/SM, wave-1 co-resident

// per-half smem: V tile db + act tile db + rows[]
#define HALF_FLOATS (2 * 128 * VSTR + 2 * RPI * VSTR + 32)
#define SMEM_BYTES  (2 * HALF_FLOATS * 4)

// ---------------- device scratch ---------------------------------------------------
__device__ int   g_cnt[NS];
__device__ int   g_off[NS];
__device__ int   g_sel_s[NASG];
__device__ float g_sel_w[NASG];
__device__ int   g_asg_b[NASG];
__device__ float g_asg_w[NASG];
__device__ int   g_map[NASG];
__device__ int   g_work[MAXITEMS];
__device__ int   g_nwork;
__device__ unsigned g_arr;                    // monotonic barrier arrive counter
__device__ unsigned g_rel;                    // monotonic barrier release counter
__device__ float g_Tpart[NASG * KQ * SUBF];   // [row][kq][col]
__device__ float g_T[(NASG + RPI) * SUBF];
__device__ float g_opart[NASG * OUTF];

// ---------------- helpers -----------------------------------------------------------
__device__ __forceinline__ void cp16(void* s, const void* g) {
    unsigned sa = (unsigned)__cvta_generic_to_shared(s);
    asm volatile("cp.async.cg.shared.global [%0], [%1], 16;\n" :: "r"(sa), "l"(g));
}
#define CP_COMMIT()  asm volatile("cp.async.commit_group;\n")
#define CP_WAIT(n)   asm volatile("cp.async.wait_group %0;\n" :: "n"(n))
#define HSYNC(h)     asm volatile("bar.sync %0, 128;" :: "r"(1 + (h)) : "memory")

__device__ __forceinline__ float4 f4add(float4 a, float4 b) {
    return make_float4(a.x + b.x, a.y + b.y, a.z + b.z, a.w + b.w);
}
__device__ __forceinline__ unsigned f2tf(float f) {
    unsigned r; asm("cvt.rna.tf32.f32 %0, %1;" : "=r"(r) : "f"(f)); return r;
}
__device__ __forceinline__ void mma_tf32(float* c, unsigned a0, unsigned a1,
                                         unsigned a2, unsigned a3,
                                         unsigned b0, unsigned b1) {
    asm volatile(
        "mma.sync.aligned.m16n8k8.row.col.f32.tf32.tf32.f32 "
        "{%0,%1,%2,%3}, {%4,%5,%6,%7}, {%8,%9}, {%0,%1,%2,%3};"
        : "+f"(c[0]), "+f"(c[1]), "+f"(c[2]), "+f"(c[3])
        : "r"(a0), "r"(a1), "r"(a2), "r"(a3), "r"(b0), "r"(b1));
}

// grid barrier: monotonic counters, safe across graph replays.
__device__ __forceinline__ void gbar(unsigned base, int k) {
    __syncthreads();
    if (threadIdx.x == 0) {
        __threadfence();
        unsigned a = atomicAdd(&g_arr, 1u) + 1u;
        if (a % GRIDN == 0u) { __threadfence(); atomicAdd(&g_rel, 1u); }
        while (*(volatile unsigned*)&g_rel < base + (unsigned)k) __nanosleep(64);
        __threadfence();
    }
    __syncthreads();
}

// ---------------- the persistent mega-kernel ---------------------------------------
__global__ void __launch_bounds__(256, 2) colak_mega(const float* __restrict__ x,
                                                     const float* __restrict__ q,
                                                     const float* __restrict__ Wk,
                                                     const float* __restrict__ bk,
                                                     const float* __restrict__ V0,
                                                     const float* __restrict__ V1,
                                                     float* __restrict__ out) {
    extern __shared__ float smem[];
    const int tid  = threadIdx.x;
    const int w    = tid >> 5;
    const int lane = tid & 31;

    __shared__ unsigned s_base;
    if (tid == 0) s_base = *(volatile unsigned*)&g_rel;
    __syncthreads();
    const unsigned base = s_base;

    // ============ phase 1: attention + top-8 + softmax (CTAs 0..63, 4 rows each) ====
    if (blockIdx.x < NB / 4) {
        float* qs = smem;                 // 4*QF floats
        __shared__ float att[4][NS];
        const int b0 = blockIdx.x * 4;

        for (int f = tid; f < 4 * (QF / 4); f += 256)
            ((float4*)qs)[f] = ((const float4*)(q + (size_t)b0 * QF))[f];
        __syncthreads();

        const float4* q4 = (const float4*)qs;
        #pragma unroll
        for (int p = 0; p < 8; p++) {
            const int s = p * 8 + w;
            const float4* wr = (const float4*)(Wk + (size_t)s * QF);
            float acc[4];
            #pragma unroll
            for (int r = 0; r < 4; r++) acc[r] = 0.f;
            #pragma unroll
            for (int i = lane; i < QF / 4; i += 32) {
                float4 a = wr[i];
                #pragma unroll
                for (int r = 0; r < 4; r++) {
                    float4 c = q4[r * (QF / 4) + i];
                    acc[r] += a.x * c.x + a.y * c.y + a.z * c.z + a.w * c.w;
                }
            }
            #pragma unroll
            for (int r = 0; r < 4; r++) {
                float v = acc[r];
                #pragma unroll
                for (int o = 16; o; o >>= 1) v += __shfl_xor_sync(0xffffffffu, v, o);
                if (lane == 0) att[r][s] = v + bk[s];
            }
        }
        __syncthreads();

        if (w < 4) {
            const int b = b0 + w;
            float v0 = att[w][lane], v1 = att[w][lane + 32];
            int r0 = 0, r1 = 0;
            #pragma unroll
            for (int j = 0; j < NS; j++) {
                float a = att[w][j];
                r0 += (a > v0) || (a == v0 && j < lane);
                r1 += (a > v1) || (a == v1 && j < lane + 32);
            }
            bool k0 = r0 < KACT, k1 = r1 < KACT;

            float m = fmaxf(k0 ? v0 : -1e30f, k1 ? v1 : -1e30f);
            #pragma unroll
            for (int o = 16; o; o >>= 1) m = fmaxf(m, __shfl_xor_sync(0xffffffffu, m, o));

            float e0 = k0 ? expf(v0 - m) : 0.f;
            float e1 = k1 ? expf(v1 - m) : 0.f;
            float sm = e0 + e1;
            #pragma unroll
            for (int o = 16; o; o >>= 1) sm += __shfl_xor_sync(0xffffffffu, sm, o);

            unsigned m0 = __ballot_sync(0xffffffffu, k0);
            unsigned m1 = __ballot_sync(0xffffffffu, k1);
            unsigned lt = (1u << lane) - 1u;
            int base1 = __popc(m0);
            if (k0) {
                int slot = __popc(m0 & lt);
                g_sel_s[b * KACT + slot] = lane;
                g_sel_w[b * KACT + slot] = e0 / sm;
            }
            if (k1) {
                int slot = base1 + __popc(m1 & lt);
                g_sel_s[b * KACT + slot] = lane + 32;
                g_sel_w[b * KACT + slot] = e1 / sm;
            }
        }
    }
    gbar(base, 1);

    // ============ phase 2: scatter (CTA 0 only) ======================================
    if (blockIdx.x == 0) {
        __shared__ int cnt[NS], off_s[NS], fill[NS], ncoff[NS];
        if (tid < NS) cnt[tid] = 0;
        __syncthreads();
        for (int idx = tid; idx < NASG; idx += 256)
            atomicAdd(&cnt[g_sel_s[idx]], 1);
        __syncthreads();

        if (tid < 32) {
            int a = cnt[lane], b = cnt[lane + 32];
            int ia = a, ib = b;
            #pragma unroll
            for (int d = 1; d < 32; d <<= 1) {
                int t = __shfl_up_sync(0xffffffffu, ia, d); if (lane >= d) ia += t;
            }
            int tota = __shfl_sync(0xffffffffu, ia, 31);
            #pragma unroll
            for (int d = 1; d < 32; d <<= 1) {
                int t = __shfl_up_sync(0xffffffffu, ib, d); if (lane >= d) ib += t;
            }
            off_s[lane]      = ia - a;
            off_s[lane + 32] = tota + ib - b;

            int nca = (a + RPI - 1) / RPI, ncb = (b + RPI - 1) / RPI;
            int inca = nca, incb = ncb;
            #pragma unroll
            for (int d = 1; d < 32; d <<= 1) {
                int t = __shfl_up_sync(0xffffffffu, inca, d); if (lane >= d) inca += t;
            }
            int totnca = __shfl_sync(0xffffffffu, inca, 31);
            #pragma unroll
            for (int d = 1; d < 32; d <<= 1) {
                int t = __shfl_up_sync(0xffffffffu, incb, d); if (lane >= d) incb += t;
            }
            ncoff[lane]      = inca - nca;
            ncoff[lane + 32] = totnca + incb - ncb;
            if (lane == 31) g_nwork = totnca + incb;
        }
        __syncthreads();

        if (tid < NS) {
            g_cnt[tid] = cnt[tid]; g_off[tid] = off_s[tid]; fill[tid] = off_s[tid];
            int bo = ncoff[tid];
            int nc = (cnt[tid] + RPI - 1) / RPI;
            for (int c = 0; c < nc; c++) g_work[bo + c] = (tid << 8) | c;
        }
        __syncthreads();
        for (int idx = tid; idx < NASG; idx += 256) {
            int s = g_sel_s[idx];
            int p = atomicAdd(&fill[s], 1);
            g_asg_b[p] = idx >> 3;
            g_asg_w[p] = g_sel_w[idx];
            g_map[idx] = p;
        }
    }
    gbar(base, 2);

    // ============ phase 3: T = X*V0^T (tf32 mma, per-half tasks) =====================
    {
        const int half = tid >> 7;
        const int ht   = tid & 127;
        float* hs   = smem + half * HALF_FLOATS;
        float* Vb0  = hs;
        float* Xb0  = hs + 2 * 128 * VSTR;
        int*   rows = (int*)(hs + 2 * 128 * VSTR + 2 * RPI * VSTR);
        const int hw = ht >> 5, hl = ht & 31;
        const int lr = hl >> 2, lc = hl & 3, jb = hw * 32;
        const int sr = ht >> 3, ss = ht & 7;
        const int ntask = g_nwork * KQ;

        for (int task = blockIdx.x * 2 + half; task < ntask; task += 2 * GRIDN) {
            const int wi = task >> 3;
            const int kq = task & 7;
            const int item = g_work[wi];
            const int s  = item >> 8;
            const int c  = item & 255;
            const int n  = g_cnt[s];
            const int m  = min(RPI, n - c * RPI);
            const int gbase = g_off[s] + c * RPI;

            if (ht < RPI) rows[ht] = g_asg_b[gbase + min(ht, m - 1)];
            HSYNC(half);

            const float* v0 = V0 + (size_t)s * SUBF * INF_;
            const int ibase = kq * 128;
            const float* xrow0 = x + (size_t)rows[sr] * INF_;
            const float* xrow1 = x + (size_t)rows[sr + 16] * INF_;

            #pragma unroll
            for (int k = 0; k < 8; k++) {
                int idx = k * 128 + ht, j = idx >> 3, seg = idx & 7;
                cp16(Vb0 + j * VSTR + seg * 4, v0 + (size_t)j * INF_ + ibase + seg * 4);
            }
            cp16(Xb0 + sr * VSTR + ss * 4, xrow0 + ibase + ss * 4);
            cp16(Xb0 + (sr + 16) * VSTR + ss * 4, xrow1 + ibase + ss * 4);
            CP_COMMIT();

            float acc[2][4][4];
            #pragma unroll
            for (int mt = 0; mt < 2; mt++)
                #pragma unroll
                for (int nt = 0; nt < 4; nt++)
                    #pragma unroll
                    for (int i = 0; i < 4; i++) acc[mt][nt][i] = 0.f;

            for (int t = 0; t < 4; t++) {
                const float* Vb = Vb0 + (t & 1) * 128 * VSTR;
                const float* Xb = Xb0 + (t & 1) * RPI * VSTR;
                if (t + 1 < 4) {
                    const int i0 = ibase + (t + 1) * 32;
                    float* vd = Vb0 + ((t + 1) & 1) * 128 * VSTR;
                    float* xd = Xb0 + ((t + 1) & 1) * RPI * VSTR;
                    #pragma unroll
                    for (int k = 0; k < 8; k++) {
                        int idx = k * 128 + ht, j = idx >> 3, seg = idx & 7;
                        cp16(vd + j * VSTR + seg * 4, v0 + (size_t)j * INF_ + i0 + seg * 4);
                    }
                    cp16(xd + sr * VSTR + ss * 4, xrow0 + i0 + ss * 4);
                    cp16(xd + (sr + 16) * VSTR + ss * 4, xrow1 + i0 + ss * 4);
                    CP_COMMIT();
                    CP_WAIT(1);
                } else {
                    CP_WAIT(0);
                }
                HSYNC(half);

                #pragma unroll
                for (int ks = 0; ks < 4; ks++) {
                    const int kk = ks * 8;
                    unsigned a[2][4];
                    #pragma unroll
                    for (int mt = 0; mt < 2; mt++) {
                        const int rb = mt * 16;
                        a[mt][0] = f2tf(Xb[(rb + lr) * VSTR + kk + lc]);
                        a[mt][1] = f2tf(Xb[(rb + lr + 8) * VSTR + kk + lc]);
                        a[mt][2] = f2tf(Xb[(rb + lr) * VSTR + kk + lc + 4]);
                        a[mt][3] = f2tf(Xb[(rb + lr + 8) * VSTR + kk + lc + 4]);
                    }
                    #pragma unroll
                    for (int nt = 0; nt < 4; nt++) {
                        const int nn = jb + nt * 8 + lr;
                        unsigned b0 = f2tf(Vb[nn * VSTR + kk + lc]);
                        unsigned b1 = f2tf(Vb[nn * VSTR + kk + lc + 4]);
                        mma_tf32(acc[0][nt], a[0][0], a[0][1], a[0][2], a[0][3], b0, b1);
                        mma_tf32(acc[1][nt], a[1][0], a[1][1], a[1][2], a[1][3], b0, b1);
                    }
                }
                HSYNC(half);
            }

            #pragma unroll
            for (int mt = 0; mt < 2; mt++) {
                #pragma unroll
                for (int nt = 0; nt < 4; nt++) {
                    const int col = jb + nt * 8 + 2 * lc;
                    const int row0 = mt * 16 + lr, row1 = row0 + 8;
                    if (row0 < m)
                        *(float2*)(g_Tpart + ((size_t)(gbase + row0) * KQ + kq) * SUBF + col)
                            = make_float2(acc[mt][nt][0], acc[mt][nt][1]);
                    if (row1 < m)
                        *(float2*)(g_Tpart + ((size_t)(gbase + row1) * KQ + kq) * SUBF + col)
                            = make_float2(acc[mt][nt][2], acc[mt][nt][3]);
                }
            }
        }
    }
    gbar(base, 3);

    // ============ phase 4: Tred (sum KQ=8 contiguous partials, apply weight) ========
    for (int idx = blockIdx.x * 256 + tid; idx < NASG * 32; idx += GRIDN * 256) {
        const int row = idx >> 5, qd = idx & 31;
        const float4* bp = (const float4*)g_Tpart + (size_t)row * KQ * 32 + qd;
        float4 t0 = bp[0],   t1 = bp[32],  t2 = bp[64],  t3 = bp[96];
        float4 t4 = bp[128], t5 = bp[160], t6 = bp[192], t7 = bp[224];
        float4 s = f4add(f4add(f4add(t0, t1), f4add(t2, t3)),
                         f4add(f4add(t4, t5), f4add(t6, t7)));
        const float wt = g_asg_w[row];
        s.x *= wt; s.y *= wt; s.z *= wt; s.w *= wt;
        *((float4*)g_T + (size_t)row * 32 + qd) = s;
    }
    gbar(base, 4);

    // ============ phase 5: O = T*V1^T (tf32 mma, per-half tasks) =====================
    {
        const int half = tid >> 7;
        const int ht   = tid & 127;
        float* hs  = smem + half * HALF_FLOATS;
        float* Vb0 = hs;
        float* Tb0 = hs + 2 * 128 * VSTR;
        const int hw = ht >> 5, hl = ht & 31;
        const int lr = hl >> 2, lc = hl & 3, ob = hw * 32;
        const int sr = ht >> 3, ss = ht & 7;
        const int ntask = g_nwork * 8;

        for (int task = blockIdx.x * 2 + half; task < ntask; task += 2 * GRIDN) {
            const int wi = task >> 3;
            const int ot = task & 7;
            const int item = g_work[wi];
            const int s  = item >> 8;
            const int c  = item & 255;
            const int n  = g_cnt[s];
            const int m  = min(RPI, n - c * RPI);
            const int gbase = g_off[s] + c * RPI;

            const float* v1 = V1 + (size_t)s * OUTF * SUBF + (size_t)ot * 128 * SUBF;
            const float* tsrc = g_T + (size_t)gbase * SUBF;

            HSYNC(half);   // previous task's smem reads complete before overwrite
            #pragma unroll
            for (int k = 0; k < 8; k++) {
                int idx = k * 128 + ht, o = idx >> 3, seg = idx & 7;
                cp16(Vb0 + o * VSTR + seg * 4, v1 + (size_t)o * SUBF + seg * 4);
            }
            cp16(Tb0 + sr * VSTR + ss * 4, tsrc + (size_t)sr * SUBF + ss * 4);
            cp16(Tb0 + (sr + 16) * VSTR + ss * 4, tsrc + (size_t)(sr + 16) * SUBF + ss * 4);
            CP_COMMIT();

            float acc[2][4][4];
            #pragma unroll
            for (int mt = 0; mt < 2; mt++)
                #pragma unroll
                for (int nt = 0; nt < 4; nt++)
                    #pragma unroll
                    for (int i = 0; i < 4; i++) acc[mt][nt][i] = 0.f;

            for (int t = 0; t < 4; t++) {
                const float* Vb = Vb0 + (t & 1) * 128 * VSTR;
                const float* Tb = Tb0 + (t & 1) * RPI * VSTR;
                if (t + 1 < 4) {
                    const int j0 = (t + 1) * 32;
                    float* vd = Vb0 + ((t + 1) & 1) * 128 * VSTR;
                    float* td = Tb0 + ((t + 1) & 1) * RPI * VSTR;
                    #pragma unroll
                    for (int k = 0; k < 8; k++) {
                        int idx = k * 128 + ht, o = idx >> 3, seg = idx & 7;
                        cp16(vd + o * VSTR + seg * 4, v1 + (size_t)o * SUBF + j0 + seg * 4);
                    }
                    cp16(td + sr * VSTR + ss * 4, tsrc + (size_t)sr * SUBF + j0 + ss * 4);
                    cp16(td + (sr + 16) * VSTR + ss * 4,
                         tsrc + (size_t)(sr + 16) * SUBF + j0 + ss * 4);
                    CP_COMMIT();
                    CP_WAIT(1);
                } else {
                    CP_WAIT(0);
                }
                HSYNC(half);

                #pragma unroll
                for (int ks = 0; ks < 4; ks++) {
                    const int kk = ks * 8;
                    unsigned a[2][4];
                    #pragma unroll
                    for (int mt = 0; mt < 2; mt++) {
                        const int rb = mt * 16;
                        a[mt][0] = f2tf(Tb[(rb + lr) * VSTR + kk + lc]);
                        a[mt][1] = f2tf(Tb[(rb + lr + 8) * VSTR + kk + lc]);
                        a[mt][2] = f2tf(Tb[(rb + lr) * VSTR + kk + lc + 4]);
                        a[mt][3] = f2tf(Tb[(rb + lr + 8) * VSTR + kk + lc + 4]);
                    }
                    #pragma unroll
                    for (int nt = 0; nt < 4; nt++) {
                        const int nn = ob + nt * 8 + lr;
                        unsigned b0 = f2tf(Vb[nn * VSTR + kk + lc]);
                        unsigned b1 = f2tf(Vb[nn * VSTR + kk + lc + 4]);
                        mma_tf32(acc[0][nt], a[0][0], a[0][1], a[0][2], a[0][3], b0, b1);
                        mma_tf32(acc[1][nt], a[1][0], a[1][1], a[1][2], a[1][3], b0, b1);
                    }
                }
                HSYNC(half);
            }

            #pragma unroll
            for (int mt = 0; mt < 2; mt++) {
                #pragma unroll
                for (int nt = 0; nt < 4; nt++) {
                    const int col = ot * 128 + ob + nt * 8 + 2 * lc;
                    const int row0 = mt * 16 + lr, row1 = row0 + 8;
                    if (row0 < m)
                        *(float2*)(g_opart + (size_t)(gbase + row0) * OUTF + col)
                            = make_float2(acc[mt][nt][0], acc[mt][nt][1]);
                    if (row1 < m)
                        *(float2*)(g_opart + (size_t)(gbase + row1) * OUTF + col)
                            = make_float2(acc[mt][nt][2], acc[mt][nt][3]);
                }
            }
        }
    }
    gbar(base, 5);

    // ============ phase 6: reduce 8 partials per batch row ===========================
    for (int idx = blockIdx.x * 256 + tid; idx < NB * 256; idx += GRIDN * 256) {
        const int b = idx >> 8, t4 = idx & 255;
        const float4* op = (const float4*)g_opart;
        const int* mp = g_map + b * KACT;   // uniform within warp (broadcast)
        float4 t0 = op[(size_t)mp[0] * 256 + t4];
        float4 t1 = op[(size_t)mp[1] * 256 + t4];
        float4 t2 = op[(size_t)mp[2] * 256 + t4];
        float4 t3 = op[(size_t)mp[3] * 256 + t4];
        float4 t4v = op[(size_t)mp[4] * 256 + t4];
        float4 t5 = op[(size_t)mp[5] * 256 + t4];
        float4 t6 = op[(size_t)mp[6] * 256 + t4];
        float4 t7 = op[(size_t)mp[7] * 256 + t4];
        float4 s = f4add(f4add(f4add(t0, t1), f4add(t2, t3)),
                         f4add(f4add(t4v, t5), f4add(t6, t7)));
        ((float4*)out)[(size_t)b * 256 + t4] = s;
    }
}

// ---------------- host launcher ------------------------------------------------------
extern "C" void kernel_launch(void* const* d_in, const int* in_sizes, int n_in,
                              void* d_out, int out_size) {
    const float* x  = (const float*)d_in[0];
    const float* q  = (const float*)d_in[1];
    const float* Wk = (const float*)d_in[2];
    const float* bk = (const float*)d_in[3];
    const float* V0 = (const float*)d_in[4];
    const float* V1 = (const float*)d_in[5];
    float* out = (float*)d_out;

    cudaFuncSetAttribute(colak_mega, cudaFuncAttributeMaxDynamicSharedMemorySize,
                         SMEM_BYTES);
    colak_mega<<<GRIDN, 256, SMEM_BYTES>>>(x, q, Wk, bk, V0, V1, out);
}

// round 16
// speedup vs baseline: 1.2895x; 1.2895x over previous
#include <cuda_runtime.h>

#define NB    256
#define NS    64
#define KACT  8
#define INF_  1024
#define OUTF  1024
#define SUBF  128
#define QF    1024
#define NASG  (NB * KACT)      // 2048 total assignments (always exact)
#define KQ    8                // k-split of T across CTAs (128 i per CTA)
#define RPI   32               // rows per work item
#define MAXITEMS 128           // sum ceil(n_s/32) <= 64 + 64
#define VSTR  36               // smem row pitch (floats): conflict-free, 16B-aligned

// PDL: producers trigger at entry; consumers park until producer grid completes.
#define PDL_TRIGGER() cudaTriggerProgrammaticLaunchCompletion()
#define PDL_SYNC()    cudaGridDependencySynchronize()

// ---------------- device scratch (static globals: no runtime allocation) ----------
__device__ int   g_cnt[NS];
__device__ int   g_off[NS];
__device__ int   g_sel_s[NASG];
__device__ float g_sel_w[NASG];
__device__ int   g_asg_b[NASG];               // compacted: batch row per assignment
__device__ float g_asg_w[NASG];               // compacted: softmax weight per assignment
__device__ int   g_map[NASG];                 // (b,slot) -> compact index
__device__ int   g_work[MAXITEMS];            // (subnet<<8)|chunk
__device__ int   g_nwork;
__device__ unsigned g_icnt[MAXITEMS];         // per-item kq completion counters (monotonic)
__device__ float g_Tpart[NASG * KQ * SUBF];   // stage-1 k-partials, layout [row][kq][col]
__device__ float g_T[(NASG + RPI) * SUBF];    // reduced, weight-applied (+pad rows)
__device__ float g_opart[NASG * OUTF];        // 8 MB partial outputs

// ---------------- helpers -----------------------------------------------------------
__device__ __forceinline__ void cp16(void* s, const void* g) {
    unsigned sa = (unsigned)__cvta_generic_to_shared(s);
    asm volatile("cp.async.cg.shared.global [%0], [%1], 16;\n" :: "r"(sa), "l"(g));
}
#define CP_COMMIT()  asm volatile("cp.async.commit_group;\n")
#define CP_WAIT(n)   asm volatile("cp.async.wait_group %0;\n" :: "n"(n))

__device__ __forceinline__ float4 f4add(float4 a, float4 b) {
    return make_float4(a.x + b.x, a.y + b.y, a.z + b.z, a.w + b.w);
}
__device__ __forceinline__ unsigned f2tf(float f) {
    unsigned r; asm("cvt.rna.tf32.f32 %0, %1;" : "=r"(r) : "f"(f)); return r;
}
__device__ __forceinline__ void mma_tf32(float* c, unsigned a0, unsigned a1,
                                         unsigned a2, unsigned a3,
                                         unsigned b0, unsigned b1) {
    asm volatile(
        "mma.sync.aligned.m16n8k8.row.col.f32.tf32.tf32.f32 "
        "{%0,%1,%2,%3}, {%4,%5,%6,%7}, {%8,%9}, {%0,%1,%2,%3};"
        : "+f"(c[0]), "+f"(c[1]), "+f"(c[2]), "+f"(c[3])
        : "r"(a0), "r"(a1), "r"(a2), "r"(a3), "r"(b0), "r"(b1));
}

// ---------------- kernel 1: attention + top-8 + softmax ---------------------------
__global__ void __launch_bounds__(256) colak_attn(const float* __restrict__ q,
                                                  const float* __restrict__ Wk,
                                                  const float* __restrict__ bk) {
    PDL_TRIGGER();
    __shared__ float qs[4 * QF];
    __shared__ float att[4][NS];
    const int b0   = blockIdx.x * 4;
    const int tid  = threadIdx.x;
    const int w    = tid >> 5;
    const int lane = tid & 31;

    for (int f = tid; f < 4 * (QF / 4); f += 256)
        ((float4*)qs)[f] = ((const float4*)(q + (size_t)b0 * QF))[f];
    __syncthreads();

    const float4* q4 = (const float4*)qs;
    #pragma unroll
    for (int p = 0; p < 8; p++) {
        const int s = p * 8 + w;
        const float4* wr = (const float4*)(Wk + (size_t)s * QF);
        float acc[4];
        #pragma unroll
        for (int r = 0; r < 4; r++) acc[r] = 0.f;
        #pragma unroll
        for (int i = lane; i < QF / 4; i += 32) {
            float4 a = wr[i];
            #pragma unroll
            for (int r = 0; r < 4; r++) {
                float4 c = q4[r * (QF / 4) + i];
                acc[r] += a.x * c.x + a.y * c.y + a.z * c.z + a.w * c.w;
            }
        }
        #pragma unroll
        for (int r = 0; r < 4; r++) {
            float v = acc[r];
            #pragma unroll
            for (int o = 16; o; o >>= 1) v += __shfl_xor_sync(0xffffffffu, v, o);
            if (lane == 0) att[r][s] = v + bk[s];
        }
    }
    __syncthreads();

    if (w < 4) {
        const int b = b0 + w;
        float v0 = att[w][lane], v1 = att[w][lane + 32];
        int r0 = 0, r1 = 0;
        #pragma unroll
        for (int j = 0; j < NS; j++) {
            float a = att[w][j];
            r0 += (a > v0) || (a == v0 && j < lane);
            r1 += (a > v1) || (a == v1 && j < lane + 32);
        }
        bool k0 = r0 < KACT, k1 = r1 < KACT;

        float m = fmaxf(k0 ? v0 : -1e30f, k1 ? v1 : -1e30f);
        #pragma unroll
        for (int o = 16; o; o >>= 1) m = fmaxf(m, __shfl_xor_sync(0xffffffffu, m, o));

        float e0 = k0 ? expf(v0 - m) : 0.f;
        float e1 = k1 ? expf(v1 - m) : 0.f;
        float sm = e0 + e1;
        #pragma unroll
        for (int o = 16; o; o >>= 1) sm += __shfl_xor_sync(0xffffffffu, sm, o);

        unsigned m0 = __ballot_sync(0xffffffffu, k0);
        unsigned m1 = __ballot_sync(0xffffffffu, k1);
        unsigned lt = (1u << lane) - 1u;
        int base1 = __popc(m0);
        if (k0) {
            int slot = __popc(m0 & lt);
            g_sel_s[b * KACT + slot] = lane;
            g_sel_w[b * KACT + slot] = e0 / sm;
        }
        if (k1) {
            int slot = base1 + __popc(m1 & lt);
            g_sel_s[b * KACT + slot] = lane + 32;
            g_sel_w[b * KACT + slot] = e1 / sm;
        }
    }
}

// ---------------- kernel 2: count + scans + compact + work list (one block) -------
__global__ void __launch_bounds__(256) colak_scatter() {
    PDL_SYNC();
    PDL_TRIGGER();
    __shared__ int cnt[NS], off_s[NS], fill[NS], ncoff[NS];
    const int tid = threadIdx.x;
    const int lane = tid & 31;
    if (tid < NS) cnt[tid] = 0;
    __syncthreads();
    for (int idx = tid; idx < NASG; idx += 256)
        atomicAdd(&cnt[g_sel_s[idx]], 1);
    __syncthreads();

    if (tid < 32) {
        int a = cnt[lane], b = cnt[lane + 32];
        int ia = a, ib = b;
        #pragma unroll
        for (int d = 1; d < 32; d <<= 1) {
            int t = __shfl_up_sync(0xffffffffu, ia, d); if (lane >= d) ia += t;
        }
        int tota = __shfl_sync(0xffffffffu, ia, 31);
        #pragma unroll
        for (int d = 1; d < 32; d <<= 1) {
            int t = __shfl_up_sync(0xffffffffu, ib, d); if (lane >= d) ib += t;
        }
        off_s[lane]      = ia - a;
        off_s[lane + 32] = tota + ib - b;

        int nca = (a + RPI - 1) / RPI, ncb = (b + RPI - 1) / RPI;
        int inca = nca, incb = ncb;
        #pragma unroll
        for (int d = 1; d < 32; d <<= 1) {
            int t = __shfl_up_sync(0xffffffffu, inca, d); if (lane >= d) inca += t;
        }
        int totnca = __shfl_sync(0xffffffffu, inca, 31);
        #pragma unroll
        for (int d = 1; d < 32; d <<= 1) {
            int t = __shfl_up_sync(0xffffffffu, incb, d); if (lane >= d) incb += t;
        }
        ncoff[lane]      = inca - nca;
        ncoff[lane + 32] = totnca + incb - ncb;
        if (lane == 31) g_nwork = totnca + incb;
    }
    __syncthreads();

    if (tid < NS) {
        g_cnt[tid] = cnt[tid]; g_off[tid] = off_s[tid]; fill[tid] = off_s[tid];
        int base = ncoff[tid];
        int nc = (cnt[tid] + RPI - 1) / RPI;
        for (int c = 0; c < nc; c++) g_work[base + c] = (tid << 8) | c;
    }
    __syncthreads();
    for (int idx = tid; idx < NASG; idx += 256) {
        int s = g_sel_s[idx];
        int p = atomicAdd(&fill[s], 1);
        g_asg_b[p] = idx >> 3;
        g_asg_w[p] = g_sel_w[idx];
        g_map[idx] = p;
    }
}

// ---------------- kernel T: stage 1 via tf32 mma + fused last-CTA k-reduction ------
// CTA = (32 asg rows of one subnet, 128-wide i-slice). 128 threads, 4 warps.
// After storing partials, the LAST of the KQ=8 CTAs for an item (detected via
// threadfence + monotonic per-item counter) sums the 8 partials in fixed kq order
// (deterministic) and writes weight-applied g_T. Removes the Tred launch.
#define SMEM_MMA_BYTES ((2 * 128 * VSTR + 2 * RPI * VSTR) * 4)

__global__ void __launch_bounds__(128) colak_T(const float* __restrict__ x,
                                               const float* __restrict__ V0) {
    PDL_SYNC();
    PDL_TRIGGER();
    if ((int)blockIdx.x >= g_nwork) return;
    const int item = g_work[blockIdx.x];
    const int s  = item >> 8;
    const int c  = item & 255;
    const int kq = blockIdx.y;            // 0..KQ-1
    const int n  = g_cnt[s];
    const int m  = min(RPI, n - c * RPI);
    const int gbase = g_off[s] + c * RPI;

    extern __shared__ float smem[];
    float* Vb0 = smem;                    // 2 x [128][VSTR]
    float* Xb0 = smem + 2 * 128 * VSTR;   // 2 x [32][VSTR]
    __shared__ int rows[RPI];

    const int tid  = threadIdx.x;
    const int w    = tid >> 5;
    const int lane = tid & 31;
    const int lr   = lane >> 2;           // 0..7
    const int lc   = lane & 3;            // 0..3
    const int jb   = w * 32;

    if (tid < RPI) rows[tid] = g_asg_b[gbase + min(tid, m - 1)];
    __syncthreads();

    const float* v0 = V0 + (size_t)s * SUBF * INF_;
    const int ibase = kq * 128;
    const int sr = tid >> 3, ss = tid & 7;
    const float* xrow0 = x + (size_t)rows[sr] * INF_;
    const float* xrow1 = x + (size_t)rows[sr + 16] * INF_;

    // prefetch tile 0
    {
        #pragma unroll
        for (int k = 0; k < 8; k++) {
            int idx = k * 128 + tid, j = idx >> 3, seg = idx & 7;
            cp16(Vb0 + j * VSTR + seg * 4, v0 + (size_t)j * INF_ + ibase + seg * 4);
        }
        cp16(Xb0 + sr * VSTR + ss * 4, xrow0 + ibase + ss * 4);
        cp16(Xb0 + (sr + 16) * VSTR + ss * 4, xrow1 + ibase + ss * 4);
        CP_COMMIT();
    }

    float acc[2][4][4];
    #pragma unroll
    for (int mt = 0; mt < 2; mt++)
        #pragma unroll
        for (int nt = 0; nt < 4; nt++)
            #pragma unroll
            for (int i = 0; i < 4; i++) acc[mt][nt][i] = 0.f;

    for (int t = 0; t < 4; t++) {
        const float* Vb = Vb0 + (t & 1) * 128 * VSTR;
        const float* Xb = Xb0 + (t & 1) * RPI * VSTR;
        if (t + 1 < 4) {
            const int i0 = ibase + (t + 1) * 32;
            float* vd = Vb0 + ((t + 1) & 1) * 128 * VSTR;
            float* xd = Xb0 + ((t + 1) & 1) * RPI * VSTR;
            #pragma unroll
            for (int k = 0; k < 8; k++) {
                int idx = k * 128 + tid, j = idx >> 3, seg = idx & 7;
                cp16(vd + j * VSTR + seg * 4, v0 + (size_t)j * INF_ + i0 + seg * 4);
            }
            cp16(xd + sr * VSTR + ss * 4, xrow0 + i0 + ss * 4);
            cp16(xd + (sr + 16) * VSTR + ss * 4, xrow1 + i0 + ss * 4);
            CP_COMMIT();
            CP_WAIT(1);
        } else {
            CP_WAIT(0);
        }
        __syncthreads();

        #pragma unroll
        for (int ks = 0; ks < 4; ks++) {
            const int kk = ks * 8;
            unsigned a[2][4];
            #pragma unroll
            for (int mt = 0; mt < 2; mt++) {
                const int rb = mt * 16;
                a[mt][0] = f2tf(Xb[(rb + lr) * VSTR + kk + lc]);
                a[mt][1] = f2tf(Xb[(rb + lr + 8) * VSTR + kk + lc]);
                a[mt][2] = f2tf(Xb[(rb + lr) * VSTR + kk + lc + 4]);
                a[mt][3] = f2tf(Xb[(rb + lr + 8) * VSTR + kk + lc + 4]);
            }
            #pragma unroll
            for (int nt = 0; nt < 4; nt++) {
                const int nn = jb + nt * 8 + lr;
                unsigned b0 = f2tf(Vb[nn * VSTR + kk + lc]);
                unsigned b1 = f2tf(Vb[nn * VSTR + kk + lc + 4]);
                mma_tf32(acc[0][nt], a[0][0], a[0][1], a[0][2], a[0][3], b0, b1);
                mma_tf32(acc[1][nt], a[1][0], a[1][1], a[1][2], a[1][3], b0, b1);
            }
        }
        __syncthreads();
    }

    // store k-partials: g_Tpart layout [row][kq][col]
    #pragma unroll
    for (int mt = 0; mt < 2; mt++) {
        #pragma unroll
        for (int nt = 0; nt < 4; nt++) {
            const int col = jb + nt * 8 + 2 * lc;
            const int row0 = mt * 16 + lr, row1 = row0 + 8;
            if (row0 < m)
                *(float2*)(g_Tpart + ((size_t)(gbase + row0) * KQ + kq) * SUBF + col)
                    = make_float2(acc[mt][nt][0], acc[mt][nt][1]);
            if (row1 < m)
                *(float2*)(g_Tpart + ((size_t)(gbase + row1) * KQ + kq) * SUBF + col)
                    = make_float2(acc[mt][nt][2], acc[mt][nt][3]);
        }
    }

    // ---- last-CTA-done k-reduction (threadFenceReduction pattern) ----
    __shared__ int amLast;
    __threadfence();
    __syncthreads();
    if (tid == 0) {
        unsigned v = atomicAdd(&g_icnt[blockIdx.x], 1u);
        amLast = ((v % KQ) == KQ - 1);
    }
    __syncthreads();
    if (!amLast) return;

    // reduce this item's m rows: fixed kq order -> deterministic
    for (int f = tid; f < RPI * 32; f += 128) {
        const int r = f >> 5, qd = f & 31;
        if (r < m) {
            const float4* bp = (const float4*)g_Tpart + ((size_t)(gbase + r) * KQ) * 32 + qd;
            float4 t0 = bp[0],   t1 = bp[32],  t2 = bp[64],  t3 = bp[96];
            float4 t4 = bp[128], t5 = bp[160], t6 = bp[192], t7 = bp[224];
            float4 sv = f4add(f4add(f4add(t0, t1), f4add(t2, t3)),
                              f4add(f4add(t4, t5), f4add(t6, t7)));
            const float wt = g_asg_w[gbase + r];
            sv.x *= wt; sv.y *= wt; sv.z *= wt; sv.w *= wt;
            *((float4*)g_T + (size_t)(gbase + r) * 32 + qd) = sv;
        }
    }
}

// ---------------- kernel O: stage 2 via tf32 mma (M=32 per CTA) --------------------
#define SMEM_O_BYTES ((2 * 128 * VSTR + 2 * RPI * VSTR) * 4)

__global__ void __launch_bounds__(128) colak_O(const float* __restrict__ V1) {
    PDL_SYNC();
    PDL_TRIGGER();
    if ((int)blockIdx.x >= g_nwork) return;
    const int item = g_work[blockIdx.x];
    const int s  = item >> 8;
    const int c  = item & 255;
    const int ot = blockIdx.y;            // 0..7
    const int n  = g_cnt[s];
    const int m  = min(RPI, n - c * RPI);
    const int gbase = g_off[s] + c * RPI;

    extern __shared__ float smem[];
    float* Vb0 = smem;                    // 2 x [128][VSTR]
    float* Tb0 = smem + 2 * 128 * VSTR;   // 2 x [32][VSTR]

    const int tid  = threadIdx.x;
    const int w    = tid >> 5;
    const int lane = tid & 31;
    const int lr   = lane >> 2;
    const int lc   = lane & 3;
    const int ob   = w * 32;

    const float* v1 = V1 + (size_t)s * OUTF * SUBF + (size_t)ot * 128 * SUBF;
    const float* tsrc = g_T + (size_t)gbase * SUBF;
    const int sr = tid >> 3, ss = tid & 7;

    // prefetch tile 0 (j0 = 0)
    {
        #pragma unroll
        for (int k = 0; k < 8; k++) {
            int idx = k * 128 + tid, o = idx >> 3, seg = idx & 7;
            cp16(Vb0 + o * VSTR + seg * 4, v1 + (size_t)o * SUBF + seg * 4);
        }
        cp16(Tb0 + sr * VSTR + ss * 4, tsrc + (size_t)sr * SUBF + ss * 4);
        cp16(Tb0 + (sr + 16) * VSTR + ss * 4, tsrc + (size_t)(sr + 16) * SUBF + ss * 4);
        CP_COMMIT();
    }

    float acc[2][4][4];
    #pragma unroll
    for (int mt = 0; mt < 2; mt++)
        #pragma unroll
        for (int nt = 0; nt < 4; nt++)
            #pragma unroll
            for (int i = 0; i < 4; i++) acc[mt][nt][i] = 0.f;

    for (int t = 0; t < 4; t++) {
        const float* Vb = Vb0 + (t & 1) * 128 * VSTR;
        const float* Tb = Tb0 + (t & 1) * RPI * VSTR;
        if (t + 1 < 4) {
            const int j0 = (t + 1) * 32;
            float* vd = Vb0 + ((t + 1) & 1) * 128 * VSTR;
            float* td = Tb0 + ((t + 1) & 1) * RPI * VSTR;
            #pragma unroll
            for (int k = 0; k < 8; k++) {
                int idx = k * 128 + tid, o = idx >> 3, seg = idx & 7;
                cp16(vd + o * VSTR + seg * 4, v1 + (size_t)o * SUBF + j0 + seg * 4);
            }
            cp16(td + sr * VSTR + ss * 4, tsrc + (size_t)sr * SUBF + j0 + ss * 4);
            cp16(td + (sr + 16) * VSTR + ss * 4,
                 tsrc + (size_t)(sr + 16) * SUBF + j0 + ss * 4);
            CP_COMMIT();
            CP_WAIT(1);
        } else {
            CP_WAIT(0);
        }
        __syncthreads();

        #pragma unroll
        for (int ks = 0; ks < 4; ks++) {
            const int kk = ks * 8;
            unsigned a[2][4];
            #pragma unroll
            for (int mt = 0; mt < 2; mt++) {
                const int rb = mt * 16;
                a[mt][0] = f2tf(Tb[(rb + lr) * VSTR + kk + lc]);
                a[mt][1] = f2tf(Tb[(rb + lr + 8) * VSTR + kk + lc]);
                a[mt][2] = f2tf(Tb[(rb + lr) * VSTR + kk + lc + 4]);
                a[mt][3] = f2tf(Tb[(rb + lr + 8) * VSTR + kk + lc + 4]);
            }
            #pragma unroll
            for (int nt = 0; nt < 4; nt++) {
                const int nn = ob + nt * 8 + lr;
                unsigned b0 = f2tf(Vb[nn * VSTR + kk + lc]);
                unsigned b1 = f2tf(Vb[nn * VSTR + kk + lc + 4]);
                mma_tf32(acc[0][nt], a[0][0], a[0][1], a[0][2], a[0][3], b0, b1);
                mma_tf32(acc[1][nt], a[1][0], a[1][1], a[1][2], a[1][3], b0, b1);
            }
        }
        __syncthreads();
    }

    #pragma unroll
    for (int mt = 0; mt < 2; mt++) {
        #pragma unroll
        for (int nt = 0; nt < 4; nt++) {
            const int col = ot * 128 + ob + nt * 8 + 2 * lc;
            const int row0 = mt * 16 + lr, row1 = row0 + 8;
            if (row0 < m)
                *(float2*)(g_opart + (size_t)(gbase + row0) * OUTF + col)
                    = make_float2(acc[mt][nt][0], acc[mt][nt][1]);
            if (row1 < m)
                *(float2*)(g_opart + (size_t)(gbase + row1) * OUTF + col)
                    = make_float2(acc[mt][nt][2], acc[mt][nt][3]);
        }
    }
}

// ---------------- kernel 4: reduce 8 partials per batch row -----------------------
__global__ void __launch_bounds__(256) colak_reduce(float* __restrict__ out) {
    PDL_SYNC();
    __shared__ int mp[KACT];
    const int b = blockIdx.x;
    const int tid = threadIdx.x;
    if (tid < KACT) mp[tid] = g_map[b * KACT + tid];
    __syncthreads();
    const float4* op = (const float4*)g_opart;

    float4 t0 = op[(size_t)mp[0] * (OUTF / 4) + tid];
    float4 t1 = op[(size_t)mp[1] * (OUTF / 4) + tid];
    float4 t2 = op[(size_t)mp[2] * (OUTF / 4) + tid];
    float4 t3 = op[(size_t)mp[3] * (OUTF / 4) + tid];
    float4 t4 = op[(size_t)mp[4] * (OUTF / 4) + tid];
    float4 t5 = op[(size_t)mp[5] * (OUTF / 4) + tid];
    float4 t6 = op[(size_t)mp[6] * (OUTF / 4) + tid];
    float4 t7 = op[(size_t)mp[7] * (OUTF / 4) + tid];

    float4 s = f4add(f4add(f4add(t0, t1), f4add(t2, t3)),
                     f4add(f4add(t4, t5), f4add(t6, t7)));
    ((float4*)out)[(size_t)b * (OUTF / 4) + tid] = s;
}

// ---------------- host launcher: PDL-chained launches -------------------------------
template <typename K, typename... Args>
static inline void launch_pdl(K kernel, dim3 grid, dim3 block, size_t smem,
                              Args... args) {
    cudaLaunchAttribute at[1];
    at[0].id = cudaLaunchAttributeProgrammaticStreamSerialization;
    at[0].val.programmaticStreamSerializationAllowed = 1;
    cudaLaunchConfig_t cfg = {};
    cfg.gridDim = grid;
    cfg.blockDim = block;
    cfg.dynamicSmemBytes = smem;
    cfg.stream = 0;
    cfg.attrs = at;
    cfg.numAttrs = 1;
    cudaLaunchKernelEx(&cfg, kernel, args...);
}

extern "C" void kernel_launch(void* const* d_in, const int* in_sizes, int n_in,
                              void* d_out, int out_size) {
    const float* x  = (const float*)d_in[0];
    const float* q  = (const float*)d_in[1];
    const float* Wk = (const float*)d_in[2];
    const float* bk = (const float*)d_in[3];
    const float* V0 = (const float*)d_in[4];
    const float* V1 = (const float*)d_in[5];
    float* out = (float*)d_out;

    colak_attn<<<NB / 4, 256>>>(q, Wk, bk);
    launch_pdl(colak_scatter, dim3(1), dim3(256), 0);
    launch_pdl(colak_T, dim3(MAXITEMS, KQ), dim3(128), SMEM_MMA_BYTES, x, V0);
    launch_pdl(colak_O, dim3(MAXITEMS, 8), dim3(128), SMEM_O_BYTES, V1);
    launch_pdl(colak_reduce, dim3(NB), dim3(256), 0, out);
}

// round 17
// speedup vs baseline: 1.3976x; 1.0839x over previous
#include <cuda_runtime.h>

#define NB    256
#define NS    64
#define KACT  8
#define INF_  1024
#define OUTF  1024
#define SUBF  128
#define QF    1024
#define NASG  (NB * KACT)      // 2048 total assignments (always exact)
#define KQ    8                // k-split of T across CTAs (128 i per CTA)
#define RPI   32               // rows per work item
#define MAXITEMS 128           // sum ceil(n_s/32) <= 64 + 64
#define VSTR  36               // smem row pitch (floats): conflict-free, 16B-aligned

// PDL: producers trigger at entry; consumers park until producer grid completes.
#define PDL_TRIGGER() cudaTriggerProgrammaticLaunchCompletion()
#define PDL_SYNC()    cudaGridDependencySynchronize()

// ---------------- device scratch (static globals: no runtime allocation) ----------
__device__ int   g_cnt[NS];
__device__ int   g_off[NS];
__device__ int   g_sel_s[NASG];
__device__ float g_sel_w[NASG];
__device__ int   g_asg_b[NASG];               // compacted: batch row per assignment
__device__ float g_asg_w[NASG];               // compacted: softmax weight per assignment
__device__ int   g_map[NASG];                 // (b,slot) -> compact index
__device__ int   g_work[MAXITEMS];            // (subnet<<8)|chunk
__device__ int   g_nwork;
__device__ float g_Tpart[NASG * KQ * SUBF];   // stage-1 k-partials, layout [row][kq][col]
__device__ float g_T[(NASG + RPI) * SUBF];    // reduced, weight-applied (+pad rows)
__device__ float g_opart[NASG * OUTF];        // 8 MB partial outputs

// ---------------- helpers -----------------------------------------------------------
__device__ __forceinline__ void cp16(void* s, const void* g) {
    unsigned sa = (unsigned)__cvta_generic_to_shared(s);
    asm volatile("cp.async.cg.shared.global [%0], [%1], 16;\n" :: "r"(sa), "l"(g));
}
#define CP_COMMIT()  asm volatile("cp.async.commit_group;\n")
#define CP_WAIT(n)   asm volatile("cp.async.wait_group %0;\n" :: "n"(n))

__device__ __forceinline__ float4 f4add(float4 a, float4 b) {
    return make_float4(a.x + b.x, a.y + b.y, a.z + b.z, a.w + b.w);
}
__device__ __forceinline__ unsigned f2tf(float f) {
    unsigned r; asm("cvt.rna.tf32.f32 %0, %1;" : "=r"(r) : "f"(f)); return r;
}
__device__ __forceinline__ void mma_tf32(float* c, unsigned a0, unsigned a1,
                                         unsigned a2, unsigned a3,
                                         unsigned b0, unsigned b1) {
    asm volatile(
        "mma.sync.aligned.m16n8k8.row.col.f32.tf32.tf32.f32 "
        "{%0,%1,%2,%3}, {%4,%5,%6,%7}, {%8,%9}, {%0,%1,%2,%3};"
        : "+f"(c[0]), "+f"(c[1]), "+f"(c[2]), "+f"(c[3])
        : "r"(a0), "r"(a1), "r"(a2), "r"(a3), "r"(b0), "r"(b1));
}

// ---------------- kernel 1: attention + top-8 + softmax ---------------------------
__global__ void __launch_bounds__(256) colak_attn(const float* __restrict__ q,
                                                  const float* __restrict__ Wk,
                                                  const float* __restrict__ bk) {
    PDL_TRIGGER();
    __shared__ float qs[4 * QF];
    __shared__ float att[4][NS];
    const int b0   = blockIdx.x * 4;
    const int tid  = threadIdx.x;
    const int w    = tid >> 5;
    const int lane = tid & 31;

    for (int f = tid; f < 4 * (QF / 4); f += 256)
        ((float4*)qs)[f] = ((const float4*)(q + (size_t)b0 * QF))[f];
    __syncthreads();

    const float4* q4 = (const float4*)qs;
    #pragma unroll
    for (int p = 0; p < 8; p++) {
        const int s = p * 8 + w;
        const float4* wr = (const float4*)(Wk + (size_t)s * QF);
        float acc[4];
        #pragma unroll
        for (int r = 0; r < 4; r++) acc[r] = 0.f;
        #pragma unroll
        for (int i = lane; i < QF / 4; i += 32) {
            float4 a = wr[i];
            #pragma unroll
            for (int r = 0; r < 4; r++) {
                float4 c = q4[r * (QF / 4) + i];
                acc[r] += a.x * c.x + a.y * c.y + a.z * c.z + a.w * c.w;
            }
        }
        #pragma unroll
        for (int r = 0; r < 4; r++) {
            float v = acc[r];
            #pragma unroll
            for (int o = 16; o; o >>= 1) v += __shfl_xor_sync(0xffffffffu, v, o);
            if (lane == 0) att[r][s] = v + bk[s];
        }
    }
    __syncthreads();

    if (w < 4) {
        const int b = b0 + w;
        float v0 = att[w][lane], v1 = att[w][lane + 32];
        int r0 = 0, r1 = 0;
        #pragma unroll
        for (int j = 0; j < NS; j++) {
            float a = att[w][j];
            r0 += (a > v0) || (a == v0 && j < lane);
            r1 += (a > v1) || (a == v1 && j < lane + 32);
        }
        bool k0 = r0 < KACT, k1 = r1 < KACT;

        float m = fmaxf(k0 ? v0 : -1e30f, k1 ? v1 : -1e30f);
        #pragma unroll
        for (int o = 16; o; o >>= 1) m = fmaxf(m, __shfl_xor_sync(0xffffffffu, m, o));

        float e0 = k0 ? expf(v0 - m) : 0.f;
        float e1 = k1 ? expf(v1 - m) : 0.f;
        float sm = e0 + e1;
        #pragma unroll
        for (int o = 16; o; o >>= 1) sm += __shfl_xor_sync(0xffffffffu, sm, o);

        unsigned m0 = __ballot_sync(0xffffffffu, k0);
        unsigned m1 = __ballot_sync(0xffffffffu, k1);
        unsigned lt = (1u << lane) - 1u;
        int base1 = __popc(m0);
        if (k0) {
            int slot = __popc(m0 & lt);
            g_sel_s[b * KACT + slot] = lane;
            g_sel_w[b * KACT + slot] = e0 / sm;
        }
        if (k1) {
            int slot = base1 + __popc(m1 & lt);
            g_sel_s[b * KACT + slot] = lane + 32;
            g_sel_w[b * KACT + slot] = e1 / sm;
        }
    }
}

// ---------------- kernel 2: count + scans + compact + work list (one block) -------
__global__ void __launch_bounds__(256) colak_scatter() {
    PDL_SYNC();
    PDL_TRIGGER();
    __shared__ int cnt[NS], off_s[NS], fill[NS], ncoff[NS];
    const int tid = threadIdx.x;
    const int lane = tid & 31;
    if (tid < NS) cnt[tid] = 0;
    __syncthreads();
    for (int idx = tid; idx < NASG; idx += 256)
        atomicAdd(&cnt[g_sel_s[idx]], 1);
    __syncthreads();

    if (tid < 32) {
        int a = cnt[lane], b = cnt[lane + 32];
        int ia = a, ib = b;
        #pragma unroll
        for (int d = 1; d < 32; d <<= 1) {
            int t = __shfl_up_sync(0xffffffffu, ia, d); if (lane >= d) ia += t;
        }
        int tota = __shfl_sync(0xffffffffu, ia, 31);
        #pragma unroll
        for (int d = 1; d < 32; d <<= 1) {
            int t = __shfl_up_sync(0xffffffffu, ib, d); if (lane >= d) ib += t;
        }
        off_s[lane]      = ia - a;
        off_s[lane + 32] = tota + ib - b;

        int nca = (a + RPI - 1) / RPI, ncb = (b + RPI - 1) / RPI;
        int inca = nca, incb = ncb;
        #pragma unroll
        for (int d = 1; d < 32; d <<= 1) {
            int t = __shfl_up_sync(0xffffffffu, inca, d); if (lane >= d) inca += t;
        }
        int totnca = __shfl_sync(0xffffffffu, inca, 31);
        #pragma unroll
        for (int d = 1; d < 32; d <<= 1) {
            int t = __shfl_up_sync(0xffffffffu, incb, d); if (lane >= d) incb += t;
        }
        ncoff[lane]      = inca - nca;
        ncoff[lane + 32] = totnca + incb - ncb;
        if (lane == 31) g_nwork = totnca + incb;
    }
    __syncthreads();

    if (tid < NS) {
        g_cnt[tid] = cnt[tid]; g_off[tid] = off_s[tid]; fill[tid] = off_s[tid];
        int base = ncoff[tid];
        int nc = (cnt[tid] + RPI - 1) / RPI;
        for (int c = 0; c < nc; c++) g_work[base + c] = (tid << 8) | c;
    }
    __syncthreads();
    for (int idx = tid; idx < NASG; idx += 256) {
        int s = g_sel_s[idx];
        int p = atomicAdd(&fill[s], 1);
        g_asg_b[p] = idx >> 3;
        g_asg_w[p] = g_sel_w[idx];
        g_map[idx] = p;
    }
}

// ---------------- kernel T: stage 1 via tf32 mma (M=32 per CTA) --------------------
#define SMEM_MMA_BYTES ((2 * 128 * VSTR + 2 * RPI * VSTR) * 4)

__global__ void __launch_bounds__(128) colak_T(const float* __restrict__ x,
                                               const float* __restrict__ V0) {
    PDL_SYNC();      // item identity depends on direct predecessor (scatter)
    PDL_TRIGGER();
    if ((int)blockIdx.x >= g_nwork) return;
    const int item = g_work[blockIdx.x];
    const int s  = item >> 8;
    const int c  = item & 255;
    const int kq = blockIdx.y;            // 0..KQ-1
    const int n  = g_cnt[s];
    const int m  = min(RPI, n - c * RPI);
    const int gbase = g_off[s] + c * RPI;

    extern __shared__ float smem[];
    float* Vb0 = smem;                    // 2 x [128][VSTR]
    float* Xb0 = smem + 2 * 128 * VSTR;   // 2 x [32][VSTR]
    __shared__ int rows[RPI];

    const int tid  = threadIdx.x;
    const int w    = tid >> 5;
    const int lane = tid & 31;
    const int lr   = lane >> 2;           // 0..7
    const int lc   = lane & 3;            // 0..3
    const int jb   = w * 32;

    if (tid < RPI) rows[tid] = g_asg_b[gbase + min(tid, m - 1)];
    __syncthreads();

    const float* v0 = V0 + (size_t)s * SUBF * INF_;
    const int ibase = kq * 128;
    const int sr = tid >> 3, ss = tid & 7;
    const float* xrow0 = x + (size_t)rows[sr] * INF_;
    const float* xrow1 = x + (size_t)rows[sr + 16] * INF_;

    // prefetch tile 0
    {
        #pragma unroll
        for (int k = 0; k < 8; k++) {
            int idx = k * 128 + tid, j = idx >> 3, seg = idx & 7;
            cp16(Vb0 + j * VSTR + seg * 4, v0 + (size_t)j * INF_ + ibase + seg * 4);
        }
        cp16(Xb0 + sr * VSTR + ss * 4, xrow0 + ibase + ss * 4);
        cp16(Xb0 + (sr + 16) * VSTR + ss * 4, xrow1 + ibase + ss * 4);
        CP_COMMIT();
    }

    float acc[2][4][4];
    #pragma unroll
    for (int mt = 0; mt < 2; mt++)
        #pragma unroll
        for (int nt = 0; nt < 4; nt++)
            #pragma unroll
            for (int i = 0; i < 4; i++) acc[mt][nt][i] = 0.f;

    for (int t = 0; t < 4; t++) {
        const float* Vb = Vb0 + (t & 1) * 128 * VSTR;
        const float* Xb = Xb0 + (t & 1) * RPI * VSTR;
        if (t + 1 < 4) {
            const int i0 = ibase + (t + 1) * 32;
            float* vd = Vb0 + ((t + 1) & 1) * 128 * VSTR;
            float* xd = Xb0 + ((t + 1) & 1) * RPI * VSTR;
            #pragma unroll
            for (int k = 0; k < 8; k++) {
                int idx = k * 128 + tid, j = idx >> 3, seg = idx & 7;
                cp16(vd + j * VSTR + seg * 4, v0 + (size_t)j * INF_ + i0 + seg * 4);
            }
            cp16(xd + sr * VSTR + ss * 4, xrow0 + i0 + ss * 4);
            cp16(xd + (sr + 16) * VSTR + ss * 4, xrow1 + i0 + ss * 4);
            CP_COMMIT();
            CP_WAIT(1);
        } else {
            CP_WAIT(0);
        }
        __syncthreads();

        #pragma unroll
        for (int ks = 0; ks < 4; ks++) {
            const int kk = ks * 8;
            unsigned a[2][4];
            #pragma unroll
            for (int mt = 0; mt < 2; mt++) {
                const int rb = mt * 16;
                a[mt][0] = f2tf(Xb[(rb + lr) * VSTR + kk + lc]);
                a[mt][1] = f2tf(Xb[(rb + lr + 8) * VSTR + kk + lc]);
                a[mt][2] = f2tf(Xb[(rb + lr) * VSTR + kk + lc + 4]);
                a[mt][3] = f2tf(Xb[(rb + lr + 8) * VSTR + kk + lc + 4]);
            }
            #pragma unroll
            for (int nt = 0; nt < 4; nt++) {
                const int nn = jb + nt * 8 + lr;
                unsigned b0 = f2tf(Vb[nn * VSTR + kk + lc]);
                unsigned b1 = f2tf(Vb[nn * VSTR + kk + lc + 4]);
                mma_tf32(acc[0][nt], a[0][0], a[0][1], a[0][2], a[0][3], b0, b1);
                mma_tf32(acc[1][nt], a[1][0], a[1][1], a[1][2], a[1][3], b0, b1);
            }
        }
        __syncthreads();
    }

    // g_Tpart layout [row][kq][col] so Tred streams contiguously
    #pragma unroll
    for (int mt = 0; mt < 2; mt++) {
        #pragma unroll
        for (int nt = 0; nt < 4; nt++) {
            const int col = jb + nt * 8 + 2 * lc;
            const int row0 = mt * 16 + lr, row1 = row0 + 8;
            if (row0 < m)
                *(float2*)(g_Tpart + ((size_t)(gbase + row0) * KQ + kq) * SUBF + col)
                    = make_float2(acc[mt][nt][0], acc[mt][nt][1]);
            if (row1 < m)
                *(float2*)(g_Tpart + ((size_t)(gbase + row1) * KQ + kq) * SUBF + col)
                    = make_float2(acc[mt][nt][2], acc[mt][nt][3]);
        }
    }
}

// ---------------- kernel Tred: sum 8 contiguous k-partials, apply weight ----------
// Pre-sync: g_asg_w is scatter-era (T's predecessor's predecessor) -> load early.
__global__ void __launch_bounds__(256) colak_Tred() {
    PDL_TRIGGER();
    const int idx = blockIdx.x * 256 + threadIdx.x;   // 0..65535
    const int row = idx >> 5, qd = idx & 31;
    const float wt = g_asg_w[row];        // pre-sync: valid (written by scatter)
    PDL_SYNC();                           // g_Tpart needs T complete
    const float4* base = (const float4*)g_Tpart + (size_t)row * KQ * 32 + qd;

    float4 t0 = base[0];
    float4 t1 = base[32];
    float4 t2 = base[64];
    float4 t3 = base[96];
    float4 t4 = base[128];
    float4 t5 = base[160];
    float4 t6 = base[192];
    float4 t7 = base[224];

    float4 s = f4add(f4add(f4add(t0, t1), f4add(t2, t3)),
                     f4add(f4add(t4, t5), f4add(t6, t7)));
    s.x *= wt; s.y *= wt; s.z *= wt; s.w *= wt;
    *((float4*)g_T + (size_t)row * 32 + qd) = s;
}

// ---------------- kernel O: stage 2 via tf32 mma (M=32 per CTA) --------------------
// Pre-sync: work item metadata (scatter-era) + V1 (const input) staged BEFORE
// gridsync -> V1 tile-0 fetch overlaps Tred. Only g_T reads are post-sync.
#define SMEM_O_BYTES ((2 * 128 * VSTR + 2 * RPI * VSTR) * 4)

__global__ void __launch_bounds__(128) colak_O(const float* __restrict__ V1) {
    PDL_TRIGGER();
    if ((int)blockIdx.x >= g_nwork) return;   // g_nwork: scatter-era, valid pre-sync
    const int item = g_work[blockIdx.x];
    const int s  = item >> 8;
    const int c  = item & 255;
    const int ot = blockIdx.y;            // 0..7
    const int n  = g_cnt[s];
    const int m  = min(RPI, n - c * RPI);
    const int gbase = g_off[s] + c * RPI;

    extern __shared__ float smem[];
    float* Vb0 = smem;                    // 2 x [128][VSTR]
    float* Tb0 = smem + 2 * 128 * VSTR;   // 2 x [32][VSTR]

    const int tid  = threadIdx.x;
    const int w    = tid >> 5;
    const int lane = tid & 31;
    const int lr   = lane >> 2;
    const int lc   = lane & 3;
    const int ob   = w * 32;

    const float* v1 = V1 + (size_t)s * OUTF * SUBF + (size_t)ot * 128 * SUBF;
    const int sr = tid >> 3, ss = tid & 7;

    // pre-sync: stage V1 tile 0 (const input) — overlaps predecessor (Tred)
    #pragma unroll
    for (int k = 0; k < 8; k++) {
        int idx = k * 128 + tid, o = idx >> 3, seg = idx & 7;
        cp16(Vb0 + o * VSTR + seg * 4, v1 + (size_t)o * SUBF + seg * 4);
    }
    CP_COMMIT();

    PDL_SYNC();                           // g_T valid from here

    const float* tsrc = g_T + (size_t)gbase * SUBF;
    cp16(Tb0 + sr * VSTR + ss * 4, tsrc + (size_t)sr * SUBF + ss * 4);
    cp16(Tb0 + (sr + 16) * VSTR + ss * 4, tsrc + (size_t)(sr + 16) * SUBF + ss * 4);
    CP_COMMIT();

    float acc[2][4][4];
    #pragma unroll
    for (int mt = 0; mt < 2; mt++)
        #pragma unroll
        for (int nt = 0; nt < 4; nt++)
            #pragma unroll
            for (int i = 0; i < 4; i++) acc[mt][nt][i] = 0.f;

    for (int t = 0; t < 4; t++) {
        const float* Vb = Vb0 + (t & 1) * 128 * VSTR;
        const float* Tb = Tb0 + (t & 1) * RPI * VSTR;
        if (t + 1 < 4) {
            const int j0 = (t + 1) * 32;
            float* vd = Vb0 + ((t + 1) & 1) * 128 * VSTR;
            float* td = Tb0 + ((t + 1) & 1) * RPI * VSTR;
            #pragma unroll
            for (int k = 0; k < 8; k++) {
                int idx = k * 128 + tid, o = idx >> 3, seg = idx & 7;
                cp16(vd + o * VSTR + seg * 4, v1 + (size_t)o * SUBF + j0 + seg * 4);
            }
            cp16(td + sr * VSTR + ss * 4, tsrc + (size_t)sr * SUBF + j0 + ss * 4);
            cp16(td + (sr + 16) * VSTR + ss * 4,
                 tsrc + (size_t)(sr + 16) * SUBF + j0 + ss * 4);
            CP_COMMIT();
            CP_WAIT(1);
        } else {
            CP_WAIT(0);
        }
        __syncthreads();

        #pragma unroll
        for (int ks = 0; ks < 4; ks++) {
            const int kk = ks * 8;
            unsigned a[2][4];
            #pragma unroll
            for (int mt = 0; mt < 2; mt++) {
                const int rb = mt * 16;
                a[mt][0] = f2tf(Tb[(rb + lr) * VSTR + kk + lc]);
                a[mt][1] = f2tf(Tb[(rb + lr + 8) * VSTR + kk + lc]);
                a[mt][2] = f2tf(Tb[(rb + lr) * VSTR + kk + lc + 4]);
                a[mt][3] = f2tf(Tb[(rb + lr + 8) * VSTR + kk + lc + 4]);
            }
            #pragma unroll
            for (int nt = 0; nt < 4; nt++) {
                const int nn = ob + nt * 8 + lr;
                unsigned b0 = f2tf(Vb[nn * VSTR + kk + lc]);
                unsigned b1 = f2tf(Vb[nn * VSTR + kk + lc + 4]);
                mma_tf32(acc[0][nt], a[0][0], a[0][1], a[0][2], a[0][3], b0, b1);
                mma_tf32(acc[1][nt], a[1][0], a[1][1], a[1][2], a[1][3], b0, b1);
            }
        }
        __syncthreads();
    }

    #pragma unroll
    for (int mt = 0; mt < 2; mt++) {
        #pragma unroll
        for (int nt = 0; nt < 4; nt++) {
            const int col = ot * 128 + ob + nt * 8 + 2 * lc;
            const int row0 = mt * 16 + lr, row1 = row0 + 8;
            if (row0 < m)
                *(float2*)(g_opart + (size_t)(gbase + row0) * OUTF + col)
                    = make_float2(acc[mt][nt][0], acc[mt][nt][1]);
            if (row1 < m)
                *(float2*)(g_opart + (size_t)(gbase + row1) * OUTF + col)
                    = make_float2(acc[mt][nt][2], acc[mt][nt][3]);
        }
    }
}

// ---------------- kernel 4: reduce 8 partials per batch row -----------------------
// Pre-sync: g_map is scatter-era -> load the 8 indices before gridsync.
__global__ void __launch_bounds__(256) colak_reduce(float* __restrict__ out) {
    __shared__ int mp[KACT];
    const int b = blockIdx.x;
    const int tid = threadIdx.x;
    if (tid < KACT) mp[tid] = g_map[b * KACT + tid];   // pre-sync: valid
    __syncthreads();
    PDL_SYNC();                                        // g_opart needs O complete
    const float4* op = (const float4*)g_opart;

    float4 t0 = op[(size_t)mp[0] * (OUTF / 4) + tid];
    float4 t1 = op[(size_t)mp[1] * (OUTF / 4) + tid];
    float4 t2 = op[(size_t)mp[2] * (OUTF / 4) + tid];
    float4 t3 = op[(size_t)mp[3] * (OUTF / 4) + tid];
    float4 t4 = op[(size_t)mp[4] * (OUTF / 4) + tid];
    float4 t5 = op[(size_t)mp[5] * (OUTF / 4) + tid];
    float4 t6 = op[(size_t)mp[6] * (OUTF / 4) + tid];
    float4 t7 = op[(size_t)mp[7] * (OUTF / 4) + tid];

    float4 s = f4add(f4add(f4add(t0, t1), f4add(t2, t3)),
                     f4add(f4add(t4, t5), f4add(t6, t7)));
    ((float4*)out)[(size_t)b * (OUTF / 4) + tid] = s;
}

// ---------------- host launcher: PDL-chained launches -------------------------------
template <typename K, typename... Args>
static inline void launch_pdl(K kernel, dim3 grid, dim3 block, size_t smem,
                              Args... args) {
    cudaLaunchAttribute at[1];
    at[0].id = cudaLaunchAttributeProgrammaticStreamSerialization;
    at[0].val.programmaticStreamSerializationAllowed = 1;
    cudaLaunchConfig_t cfg = {};
    cfg.gridDim = grid;
    cfg.blockDim = block;
    cfg.dynamicSmemBytes = smem;
    cfg.stream = 0;
    cfg.attrs = at;
    cfg.numAttrs = 1;
    cudaLaunchKernelEx(&cfg, kernel, args...);
}

extern "C" void kernel_launch(void* const* d_in, const int* in_sizes, int n_in,
                              void* d_out, int out_size) {
    const float* x  = (const float*)d_in[0];
    const float* q  = (const float*)d_in[1];
    const float* Wk = (const float*)d_in[2];
    const float* bk = (const float*)d_in[3];
    const float* V0 = (const float*)d_in[4];
    const float* V1 = (const float*)d_in[5];
    float* out = (float*)d_out;

    colak_attn<<<NB / 4, 256>>>(q, Wk, bk);
    launch_pdl(colak_scatter, dim3(1), dim3(256), 0);
    launch_pdl(colak_T, dim3(MAXITEMS, KQ), dim3(128), SMEM_MMA_BYTES, x, V0);
    launch_pdl(colak_Tred, dim3(NASG * SUBF / (256 * 4)), dim3(256), 0);
    launch_pdl(colak_O, dim3(MAXITEMS, 8), dim3(128), SMEM_O_BYTES, V1);
    launch_pdl(colak_reduce, dim3(NB), dim3(256), 0, out);
}